// round 3
// baseline (speedup 1.0000x reference)
#include <cuda_runtime.h>
#include <math.h>

#define T_STEPS 512
#define BATCH   64
#define TB      (T_STEPS*BATCH)   // 32768
#define EMB     400
#define NHID    1150

typedef unsigned long long u64;

// packed fp32x2 FMA: d = a*b + d  (Blackwell FFMA2, only reachable via PTX)
__device__ __forceinline__ void fma2(u64& d, u64 a, u64 b) {
    asm("fma.rn.f32x2 %0, %1, %2, %0;" : "+l"(d) : "l"(a), "l"(b));
}
__device__ __forceinline__ float2 u2f2(u64 v) {
    float2 r; asm("mov.b64 {%0,%1}, %2;" : "=f"(r.x), "=f"(r.y) : "l"(v)); return r;
}

// ---------------- scratch (device globals: allocation-free) ----------------
__device__ float g_emb[TB*EMB];                         // 52.4 MB
__device__ float g_xg[(size_t)TB*4*NHID];               // 603 MB (max 32768*4600)
__device__ float g_h[2][1152*64];                       // double-buffered hidden state, k-major [k][m]
__device__ unsigned g_count;                            // grid barrier state (zero-init)
__device__ unsigned g_gen;

// ---------------- embedding gather ----------------
__global__ void embed_kernel(const int* __restrict__ tok, const float* __restrict__ ew) {
    int i = blockIdx.x * blockDim.x + threadIdx.x;      // over TB * 100 float4
    if (i < TB * 100) {
        int r = i / 100, c = i - r * 100;
        const float4* src = (const float4*)(ew + (size_t)tok[r] * EMB);
        ((float4*)g_emb)[(size_t)r * 100 + c] = src[c];
    }
}

// ---------------- input projection GEMM (f32x2, 128x128 tile, 8x8/thread) ----
// Y[m][n] = sum_k X[m][k]*W[n][k] + bi[n]+bh[n]
#define BM 128
#define BN 128
#define BK 16
#define SSTR 18   // smem row stride (floats): 8B-aligned, conflict-free for tx*72B

__global__ void __launch_bounds__(256, 1) proj_kernel(
    const float* __restrict__ X, const float* __restrict__ W,
    const float* __restrict__ bi, const float* __restrict__ bh,
    float* __restrict__ Y, int N, int K)
{
    __shared__ float As[2][BM * SSTR];
    __shared__ float Bs[2][BN * SSTR];

    int tid = threadIdx.x;
    int tx = tid & 15, ty = tid >> 4;          // tx: n-dir, ty: m-dir (strided tiles)
    int mb = blockIdx.y * BM;
    int nb = blockIdx.x * BN;

    int ntiles = (K + BK - 1) / BK;

    // ---- stage tile 0 ----
#pragma unroll
    for (int p = 0; p < 8; p++) {
        int e = tid + p * 256;
        int m = e >> 4, kk = e & 15;
        As[0][m * SSTR + kk] = (kk < K) ? X[(size_t)(mb + m) * K + kk] : 0.f;
        int n = m;
        Bs[0][n * SSTR + kk] = (kk < K && nb + n < N) ? W[(size_t)(nb + n) * K + kk] : 0.f;
    }
    __syncthreads();

    u64 acc2[64];
#pragma unroll
    for (int i = 0; i < 64; i++) acc2[i] = 0ull;

    for (int t = 0; t < ntiles; t++) {
        int cur = t & 1, nxt = cur ^ 1;
        int k0n = (t + 1) * BK;

        // prefetch next tile into registers (global loads issue early)
        float ra[8], rb[8];
        if (t + 1 < ntiles) {
#pragma unroll
            for (int p = 0; p < 8; p++) {
                int e = tid + p * 256;
                int m = e >> 4, kk = e & 15;
                ra[p] = (k0n + kk < K) ? X[(size_t)(mb + m) * K + k0n + kk] : 0.f;
                rb[p] = (k0n + kk < K && nb + m < N) ? W[(size_t)(nb + m) * K + k0n + kk] : 0.f;
            }
        }

        // compute on current tile: K-packed f32x2, 8x8 strided thread tile
#pragma unroll
        for (int kk = 0; kk < BK; kk += 2) {
            u64 a2[8], b2[8];
#pragma unroll
            for (int i = 0; i < 8; i++)
                a2[i] = *(const u64*)&As[cur][(ty + 16 * i) * SSTR + kk];
#pragma unroll
            for (int j = 0; j < 8; j++)
                b2[j] = *(const u64*)&Bs[cur][(tx + 16 * j) * SSTR + kk];
#pragma unroll
            for (int i = 0; i < 8; i++)
#pragma unroll
                for (int j = 0; j < 8; j++)
                    fma2(acc2[i * 8 + j], a2[i], b2[j]);
        }

        if (t + 1 < ntiles) {
#pragma unroll
            for (int p = 0; p < 8; p++) {
                int e = tid + p * 256;
                int m = e >> 4, kk = e & 15;
                As[nxt][m * SSTR + kk] = ra[p];
                Bs[nxt][m * SSTR + kk] = rb[p];
            }
        }
        __syncthreads();
    }

    // epilogue: horizontal add of the k-pair halves + bias
#pragma unroll
    for (int j = 0; j < 8; j++) {
        int n = nb + tx + 16 * j;
        if (n >= N) continue;
        float bias = bi[n] + bh[n];
#pragma unroll
        for (int i = 0; i < 8; i++) {
            int m = mb + ty + 16 * i;
            float2 v = u2f2(acc2[i * 8 + j]);
            Y[(size_t)m * N + n] = v.x + v.y + bias;
        }
    }
}

// ---------------- zero hidden state buffer 0 ----------------
__global__ void zero_h_kernel(int n) {
    int i = blockIdx.x * blockDim.x + threadIdx.x;
    if (i < n) g_h[0][i] = 0.f;
}

// ---------------- grid barrier (all blocks co-resident) ----------------
__device__ __forceinline__ void grid_barrier(int nb) {
    __threadfence();
    __syncthreads();
    if (threadIdx.x == 0) {
        volatile unsigned* genp = &g_gen;
        unsigned g = *genp;
        unsigned old = atomicAdd(&g_count, 1u);
        if (old == (unsigned)(nb - 1)) {
            g_count = 0;
            __threadfence();
            atomicAdd(&g_gen, 1u);
        } else {
            while (*genp == g) { }
        }
    }
    __syncthreads();
    __threadfence();
}

__device__ __forceinline__ float sigmoidf_(float x) { return 1.f / (1.f + expf(-x)); }

// ---------------- persistent LSTM scan ----------------
// H: real hidden size, HP: padded (mult of 64), U: hidden units per block, NT: n-tile per thread
// Block owns gate rows n = q*U + ui (q=0..3 gates i,f,g,o), units [u0, u0+U).
template<int H, int HP, int U, int NT>
__global__ void __launch_bounds__(128, 1) scan_kernel(
    const float* __restrict__ xg, const float* __restrict__ whh,
    float* __restrict__ out, int nb)
{
    constexpr int N  = 4 * U;       // gate rows per block
    constexpr int NS = N + 1;       // padded gate_s stride
    constexpr int KC = 64;
    constexpr int NCH = HP / KC;
    constexpr int G  = 4 * H;

    extern __shared__ float sm[];
    float* Ws     = sm;                   // [HP][N]
    float* hs     = Ws + HP * N;          // [KC][64]
    float* gate_s = hs + KC * 64;         // [64][NS]
    float* cs     = gate_s + 64 * NS;     // [64][U+1]

    int tid = threadIdx.x;
    int u0 = blockIdx.x * U;
    int nx = tid & 7, my = tid >> 3;      // nx: 0..7 (n-dir), my: 0..15 (m-dir)

    // Load W_hh chunk into SMEM, [k][n] layout, zero padding
    for (int idx = tid; idx < N * HP; idx += 128) {
        int n = idx / HP, k = idx - n * HP;
        int q = n / U, ui = n - q * U;
        int unit = u0 + ui;
        float v = 0.f;
        if (k < H && unit < H) v = whh[((size_t)(q * H + unit)) * H + k];
        Ws[k * N + n] = v;
    }
    for (int idx = tid; idx < 64 * (U + 1); idx += 128) cs[idx] = 0.f;
    __syncthreads();

    for (int t = 0; t < T_STEPS; t++) {
        int r = t & 1, w = r ^ 1;
        const float* hb = g_h[r];
        float* hw = g_h[w];

        float acc[4][NT];
#pragma unroll
        for (int i = 0; i < 4; i++)
#pragma unroll
            for (int j = 0; j < NT; j++) acc[i][j] = 0.f;

        // prefetch chunk 0 of h (L2 loads: bypass L1, other SMs rewrote it)
        float4 pf[8];
        {
            const float4* src = (const float4*)hb;
#pragma unroll
            for (int j = 0; j < 8; j++) pf[j] = __ldcg(&src[j * 128 + tid]);
        }

        for (int c = 0; c < NCH; c++) {
            __syncthreads();
#pragma unroll
            for (int j = 0; j < 8; j++) ((float4*)hs)[j * 128 + tid] = pf[j];
            __syncthreads();
            if (c + 1 < NCH) {
                const float4* src = (const float4*)(hb + (c + 1) * KC * 64);
#pragma unroll
                for (int j = 0; j < 8; j++) pf[j] = __ldcg(&src[j * 128 + tid]);
            }
#pragma unroll 8
            for (int k = 0; k < KC; k++) {
                float4 hv = *(const float4*)&hs[k * 64 + my * 4];
                float wv[NT];
                if constexpr (NT == 4) {
                    float4 w4 = *(const float4*)&Ws[(c * KC + k) * N + nx * 4];
                    wv[0] = w4.x; wv[1] = w4.y; wv[2] = w4.z; wv[3] = w4.w;
                } else {
                    float2 w2 = *(const float2*)&Ws[(c * KC + k) * N + nx * 2];
                    wv[0] = w2.x; wv[1] = w2.y;
                }
                float hvv[4] = {hv.x, hv.y, hv.z, hv.w};
#pragma unroll
                for (int i = 0; i < 4; i++)
#pragma unroll
                    for (int j = 0; j < NT; j++) acc[i][j] += hvv[i] * wv[j];
            }
        }

        // exchange gates via SMEM
#pragma unroll
        for (int i = 0; i < 4; i++) {
            int m = my * 4 + i;
#pragma unroll
            for (int j = 0; j < NT; j++) gate_s[m * NS + nx * NT + j] = acc[i][j];
        }
        __syncthreads();

        // epilogue: each thread handles U/2 (m, unit) pairs
        const float* xgt = xg + (size_t)t * 64 * G;
#pragma unroll
        for (int j = 0; j < U / 2; j++) {
            int p = j * 128 + tid;
            int uu = p % U;
            int m  = p / U;
            int unit = u0 + uu;
            float hval = 0.f;
            if (unit < H) {
                const float* xr = xgt + (size_t)m * G + unit;
                float iraw = gate_s[m * NS + 0 * U + uu] + xr[0];
                float fraw = gate_s[m * NS + 1 * U + uu] + xr[H];
                float graw = gate_s[m * NS + 2 * U + uu] + xr[2 * H];
                float oraw = gate_s[m * NS + 3 * U + uu] + xr[3 * H];
                float cold = cs[m * (U + 1) + uu];
                float cnew = sigmoidf_(fraw) * cold + sigmoidf_(iraw) * tanhf(graw);
                cs[m * (U + 1) + uu] = cnew;
                hval = sigmoidf_(oraw) * tanhf(cnew);
                out[((size_t)t * 64 + m) * H + unit] = hval;
            }
            hw[(u0 + uu) * 64 + m] = hval;
        }
        grid_barrier(nb);
    }
}

// ---------------- launch ----------------
extern "C" void kernel_launch(void* const* d_in, const int* in_sizes, int n_in,
                              void* d_out, int out_size)
{
    (void)in_sizes; (void)n_in; (void)out_size;
    const int*   tok = (const int*)d_in[0];
    const float* ew  = (const float*)d_in[1];
    const float* wih[3] = {(const float*)d_in[2], (const float*)d_in[6],  (const float*)d_in[10]};
    const float* whh[3] = {(const float*)d_in[3], (const float*)d_in[7],  (const float*)d_in[11]};
    const float* bih[3] = {(const float*)d_in[4], (const float*)d_in[8],  (const float*)d_in[12]};
    const float* bhh[3] = {(const float*)d_in[5], (const float*)d_in[9],  (const float*)d_in[13]};

    float* out  = (float*)d_out;
    float* out0 = out;
    float* out1 = out0 + (size_t)TB * NHID;
    float* out2 = out1 + (size_t)TB * NHID;

    void* emb_p = nullptr; cudaGetSymbolAddress(&emb_p, g_emb);
    void* xg_p  = nullptr; cudaGetSymbolAddress(&xg_p,  g_xg);
    const float* embf = (const float*)emb_p;
    float* xgf = (float*)xg_p;

    // dynamic SMEM sizes
    const int SMEM0 = (1152 * 32 + 64 * 64 + 64 * 33 + 64 * 9) * 4;   // 174,592 B
    const int SMEM2 = (448 * 16 + 64 * 64 + 64 * 17 + 64 * 5) * 4;    //  50,688 B
    cudaFuncSetAttribute(scan_kernel<1150, 1152, 8, 4>,
                         cudaFuncAttributeMaxDynamicSharedMemorySize, SMEM0);
    cudaFuncSetAttribute(scan_kernel<400, 448, 4, 2>,
                         cudaFuncAttributeMaxDynamicSharedMemorySize, SMEM2);

    // embedding
    embed_kernel<<<(TB * 100 + 255) / 256, 256>>>(tok, ew);

    dim3 pgBig((4600 + BN - 1) / BN, TB / BM);   // 36 x 256
    dim3 pgSm((1600 + BN - 1) / BN, TB / BM);    // 13 x 256
    const int ZN = 1152 * 64;

    // ---- layer 0: 400 -> 1150 ----
    proj_kernel<<<pgBig, 256>>>(embf, wih[0], bih[0], bhh[0], xgf, 4 * NHID, EMB);
    zero_h_kernel<<<(ZN + 255) / 256, 256>>>(ZN);
    scan_kernel<1150, 1152, 8, 4><<<144, 128, SMEM0>>>(xgf, whh[0], out0, 144);

    // ---- layer 1: 1150 -> 1150 ----
    proj_kernel<<<pgBig, 256>>>(out0, wih[1], bih[1], bhh[1], xgf, 4 * NHID, NHID);
    zero_h_kernel<<<(ZN + 255) / 256, 256>>>(ZN);
    scan_kernel<1150, 1152, 8, 4><<<144, 128, SMEM0>>>(xgf, whh[1], out1, 144);

    // ---- layer 2: 1150 -> 400 ----
    proj_kernel<<<pgSm, 256>>>(out1, wih[2], bih[2], bhh[2], xgf, 4 * 400, NHID);
    zero_h_kernel<<<(ZN + 255) / 256, 256>>>(ZN);
    scan_kernel<400, 448, 4, 2><<<112, 128, SMEM2>>>(xgf, whh[2], out2, 112);
}

// round 5
// speedup vs baseline: 1.2258x; 1.2258x over previous
#include <cuda_runtime.h>
#include <cuda_bf16.h>
#include <math.h>
#include <stdint.h>

#define T_STEPS 512
#define BATCH   64
#define TB      (T_STEPS*BATCH)   // 32768
#define EMB     400
#define NHID    1150

// ================= PTX helpers (sm_80+ only — no 'a' features!) =================
__device__ __forceinline__ uint32_t smem_u32(const void* p) {
    uint32_t a;
    asm("{ .reg .u64 t; cvta.to.shared.u64 t, %1; cvt.u32.u64 %0, t; }" : "=r"(a) : "l"(p));
    return a;
}
__device__ __forceinline__ void ldsm_x4(uint32_t* r, uint32_t addr) {
    asm volatile("ldmatrix.sync.aligned.m8n8.x4.shared.b16 {%0,%1,%2,%3}, [%4];"
        : "=r"(r[0]), "=r"(r[1]), "=r"(r[2]), "=r"(r[3]) : "r"(addr));
}
__device__ __forceinline__ void ldsm_x2(uint32_t* r, uint32_t addr) {
    asm volatile("ldmatrix.sync.aligned.m8n8.x2.shared.b16 {%0,%1}, [%2];"
        : "=r"(r[0]), "=r"(r[1]) : "r"(addr));
}
__device__ __forceinline__ void mma_bf16(float* c, const uint32_t* a, const uint32_t* b) {
    asm volatile("mma.sync.aligned.m16n8k16.row.col.f32.bf16.bf16.f32 "
        "{%0,%1,%2,%3}, {%4,%5,%6,%7}, {%8,%9}, {%0,%1,%2,%3};"
        : "+f"(c[0]), "+f"(c[1]), "+f"(c[2]), "+f"(c[3])
        : "r"(a[0]), "r"(a[1]), "r"(a[2]), "r"(a[3]), "r"(b[0]), "r"(b[1]));
}

// ================= scratch (device globals) =================
__device__ float g_emb[TB*EMB];                          // 52.4 MB
__device__ float g_xg[(size_t)TB*4*NHID];                // 603 MB
__device__ float g_h[2][1152*64];
__device__ unsigned g_count;
__device__ unsigned g_gen;
__device__ __align__(16) __nv_bfloat16 g_xh[(size_t)TB*1152];   // 75.5 MB
__device__ __align__(16) __nv_bfloat16 g_xl[(size_t)TB*1152];   // 75.5 MB
__device__ __align__(16) __nv_bfloat16 g_wh[4608ull*1152];      // 10.6 MB
__device__ __align__(16) __nv_bfloat16 g_wl[4608ull*1152];      // 10.6 MB

// ================= embedding gather =================
__global__ void embed_kernel(const int* __restrict__ tok, const float* __restrict__ ew) {
    int i = blockIdx.x * blockDim.x + threadIdx.x;
    if (i < TB * 100) {
        int r = i / 100, c = i - r * 100;
        const float4* src = (const float4*)(ew + (size_t)tok[r] * EMB);
        ((float4*)g_emb)[(size_t)r * 100 + c] = src[c];
    }
}

// ================= bf16 hi/lo split conversions =================
__global__ void conv_x_kernel(const float* __restrict__ X, int K, int KP,
                              __nv_bfloat16* __restrict__ hi, __nv_bfloat16* __restrict__ lo) {
    size_t idx = (size_t)blockIdx.x * blockDim.x + threadIdx.x;
    if (idx >= (size_t)TB * KP) return;
    int k = (int)(idx % KP);
    size_t r = idx / KP;
    float v = (k < K) ? X[r * K + k] : 0.f;
    __nv_bfloat16 h = __float2bfloat16_rn(v);
    hi[idx] = h;
    lo[idx] = __float2bfloat16_rn(v - __bfloat162float(h));
}
__global__ void conv_w_kernel(const float* __restrict__ W, int N, int K, int KP, int NP,
                              __nv_bfloat16* __restrict__ hi, __nv_bfloat16* __restrict__ lo) {
    size_t idx = (size_t)blockIdx.x * blockDim.x + threadIdx.x;
    if (idx >= (size_t)NP * KP) return;
    int k = (int)(idx % KP);
    size_t n = idx / KP;
    float v = (k < K && n < (size_t)N) ? W[n * K + k] : 0.f;
    __nv_bfloat16 h = __float2bfloat16_rn(v);
    hi[idx] = h;
    lo[idx] = __float2bfloat16_rn(v - __bfloat162float(h));
}

// ================= HMMA projection GEMM =================
// Y[m][n] = sum_k X[m][k]*W[n][k] + bi[n]+bh[n]  via bf16x3 (hi*hi + lo*hi + hi*lo)
// 128x128 block tile, 8 warps (2m x 4n), warp tile 64x32, k-tile 32 bf16.
// SMEM tiles padded to stride 40 halves (80 B): conflict-free stores + ldmatrix.
#define PSTR 40

template<int KP>
__global__ void __launch_bounds__(256, 1) proj_hmma_kernel(
    const __nv_bfloat16* __restrict__ Xhi, const __nv_bfloat16* __restrict__ Xlo,
    const __nv_bfloat16* __restrict__ Whi, const __nv_bfloat16* __restrict__ Wlo,
    const float* __restrict__ bi, const float* __restrict__ bh,
    float* __restrict__ Y, int Nreal)
{
    __shared__ __align__(16) __nv_bfloat16 As[2][128 * PSTR];
    __shared__ __align__(16) __nv_bfloat16 Bs[2][128 * PSTR];

    constexpr int KT0 = KP / 32;        // k-tiles per pass
    const int KT = 3 * KT0;             // hi*hi, lo*hi, hi*lo

    int tid = threadIdx.x;
    int wid = tid >> 5, lane = tid & 31;
    int warp_m = wid & 1, warp_n = wid >> 1;
    size_t mb = (size_t)blockIdx.y * 128;
    size_t nb = (size_t)blockIdx.x * 128;

    const __nv_bfloat16* Asrc[3] = {Xhi, Xlo, Xhi};
    const __nv_bfloat16* Bsrc[3] = {Whi, Whi, Wlo};

    uint32_t as0 = smem_u32(&As[0][0]);
    uint32_t bs0 = smem_u32(&Bs[0][0]);

    // staging index: e in [0,512): row = e>>2 (0..127), seg = e&3 (16B units)
    int srow = tid >> 2, sseg = tid & 3;          // iter 0
    int srow1 = (tid + 256) >> 2, sseg1 = (tid + 256) & 3;

    float acc[4][4][4];
#pragma unroll
    for (int i = 0; i < 4; i++)
#pragma unroll
        for (int j = 0; j < 4; j++)
#pragma unroll
            for (int q = 0; q < 4; q++) acc[i][j][q] = 0.f;

    // ---- stage tile 0 ----
    {
        const __nv_bfloat16* ax = Asrc[0];
        const __nv_bfloat16* bx = Bsrc[0];
        *(uint4*)&As[0][srow * PSTR + sseg * 8]   = *(const uint4*)(ax + (mb + srow) * KP + sseg * 8);
        *(uint4*)&As[0][srow1 * PSTR + sseg1 * 8] = *(const uint4*)(ax + (mb + srow1) * KP + sseg1 * 8);
        *(uint4*)&Bs[0][srow * PSTR + sseg * 8]   = *(const uint4*)(bx + (nb + srow) * KP + sseg * 8);
        *(uint4*)&Bs[0][srow1 * PSTR + sseg1 * 8] = *(const uint4*)(bx + (nb + srow1) * KP + sseg1 * 8);
    }
    __syncthreads();

    for (int t = 0; t < KT; t++) {
        int cur = t & 1, nxt = cur ^ 1;

        // prefetch next tile into registers
        uint4 pa0, pa1, pb0, pb1;
        if (t + 1 < KT) {
            int tp = t + 1;
            int pass = tp / KT0, c = tp - pass * KT0;
            const __nv_bfloat16* ax = Asrc[pass];
            const __nv_bfloat16* bx = Bsrc[pass];
            int col = c * 32;
            pa0 = *(const uint4*)(ax + (mb + srow) * KP + col + sseg * 8);
            pa1 = *(const uint4*)(ax + (mb + srow1) * KP + col + sseg1 * 8);
            pb0 = *(const uint4*)(bx + (nb + srow) * KP + col + sseg * 8);
            pb1 = *(const uint4*)(bx + (nb + srow1) * KP + col + sseg1 * 8);
        }

        // compute on current tile: 2 k-frags of 16
        uint32_t abase = as0 + cur * (128 * PSTR * 2);
        uint32_t bbase = bs0 + cur * (128 * PSTR * 2);
#pragma unroll
        for (int kf = 0; kf < 2; kf++) {
            uint32_t a[4][4], b[4][2];
#pragma unroll
            for (int fm = 0; fm < 4; fm++) {
                uint32_t addr = abase +
                    ((warp_m * 64 + fm * 16 + (lane & 15)) * PSTR + kf * 16 + (lane >> 4) * 8) * 2;
                ldsm_x4(a[fm], addr);
            }
#pragma unroll
            for (int fn = 0; fn < 4; fn++) {
                uint32_t addr = bbase +
                    ((warp_n * 32 + fn * 8 + (lane & 7)) * PSTR + kf * 16 + ((lane >> 3) & 1) * 8) * 2;
                ldsm_x2(b[fn], addr);
            }
#pragma unroll
            for (int fm = 0; fm < 4; fm++)
#pragma unroll
                for (int fn = 0; fn < 4; fn++)
                    mma_bf16(acc[fm][fn], a[fm], b[fn]);
        }

        if (t + 1 < KT) {
            *(uint4*)&As[nxt][srow * PSTR + sseg * 8]   = pa0;
            *(uint4*)&As[nxt][srow1 * PSTR + sseg1 * 8] = pa1;
            *(uint4*)&Bs[nxt][srow * PSTR + sseg * 8]   = pb0;
            *(uint4*)&Bs[nxt][srow1 * PSTR + sseg1 * 8] = pb1;
        }
        __syncthreads();
    }

    // ---- epilogue: fused bias, float2 stores ----
    int group = lane >> 2, tig = lane & 3;
#pragma unroll
    for (int fn = 0; fn < 4; fn++) {
        int n = (int)nb + warp_n * 32 + fn * 8 + 2 * tig;
        if (n < Nreal) {
            float bx = bi[n] + bh[n];
            float by = bi[n + 1] + bh[n + 1];
#pragma unroll
            for (int fm = 0; fm < 4; fm++) {
                size_t m = mb + warp_m * 64 + fm * 16 + group;
                float2 v0 = {acc[fm][fn][0] + bx, acc[fm][fn][1] + by};
                *(float2*)&Y[m * (size_t)Nreal + n] = v0;
                float2 v1 = {acc[fm][fn][2] + bx, acc[fm][fn][3] + by};
                *(float2*)&Y[(m + 8) * (size_t)Nreal + n] = v1;
            }
        }
    }
}

// ================= zero hidden state =================
__global__ void zero_h_kernel(int n) {
    int i = blockIdx.x * blockDim.x + threadIdx.x;
    if (i < n) g_h[0][i] = 0.f;
}

// ================= grid barrier =================
__device__ __forceinline__ void grid_barrier(int nb) {
    __threadfence();
    __syncthreads();
    if (threadIdx.x == 0) {
        volatile unsigned* genp = &g_gen;
        unsigned g = *genp;
        unsigned old = atomicAdd(&g_count, 1u);
        if (old == (unsigned)(nb - 1)) {
            g_count = 0;
            __threadfence();
            atomicAdd(&g_gen, 1u);
        } else {
            while (*genp == g) { }
        }
    }
    __syncthreads();
    __threadfence();
}

__device__ __forceinline__ float sigmoidf_(float x) { return 1.f / (1.f + expf(-x)); }

// ================= persistent LSTM scan (unchanged from best) =================
template<int H, int HP, int U, int NT>
__global__ void __launch_bounds__(128, 1) scan_kernel(
    const float* __restrict__ xg, const float* __restrict__ whh,
    float* __restrict__ out, int nb)
{
    constexpr int N  = 4 * U;
    constexpr int NS = N + 1;
    constexpr int KC = 64;
    constexpr int NCH = HP / KC;
    constexpr int G  = 4 * H;

    extern __shared__ float sm[];
    float* Ws     = sm;
    float* hs     = Ws + HP * N;
    float* gate_s = hs + KC * 64;
    float* cs     = gate_s + 64 * NS;

    int tid = threadIdx.x;
    int u0 = blockIdx.x * U;
    int nx = tid & 7, my = tid >> 3;

    for (int idx = tid; idx < N * HP; idx += 128) {
        int n = idx / HP, k = idx - n * HP;
        int q = n / U, ui = n - q * U;
        int unit = u0 + ui;
        float v = 0.f;
        if (k < H && unit < H) v = whh[((size_t)(q * H + unit)) * H + k];
        Ws[k * N + n] = v;
    }
    for (int idx = tid; idx < 64 * (U + 1); idx += 128) cs[idx] = 0.f;
    __syncthreads();

    for (int t = 0; t < T_STEPS; t++) {
        int r = t & 1, w = r ^ 1;
        const float* hb = g_h[r];
        float* hw = g_h[w];

        float acc[4][NT];
#pragma unroll
        for (int i = 0; i < 4; i++)
#pragma unroll
            for (int j = 0; j < NT; j++) acc[i][j] = 0.f;

        float4 pf[8];
        {
            const float4* src = (const float4*)hb;
#pragma unroll
            for (int j = 0; j < 8; j++) pf[j] = __ldcg(&src[j * 128 + tid]);
        }

        for (int c = 0; c < NCH; c++) {
            __syncthreads();
#pragma unroll
            for (int j = 0; j < 8; j++) ((float4*)hs)[j * 128 + tid] = pf[j];
            __syncthreads();
            if (c + 1 < NCH) {
                const float4* src = (const float4*)(hb + (c + 1) * KC * 64);
#pragma unroll
                for (int j = 0; j < 8; j++) pf[j] = __ldcg(&src[j * 128 + tid]);
            }
#pragma unroll 8
            for (int k = 0; k < KC; k++) {
                float4 hv = *(const float4*)&hs[k * 64 + my * 4];
                float wv[NT];
                if constexpr (NT == 4) {
                    float4 w4 = *(const float4*)&Ws[(c * KC + k) * N + nx * 4];
                    wv[0] = w4.x; wv[1] = w4.y; wv[2] = w4.z; wv[3] = w4.w;
                } else {
                    float2 w2 = *(const float2*)&Ws[(c * KC + k) * N + nx * 2];
                    wv[0] = w2.x; wv[1] = w2.y;
                }
                float hvv[4] = {hv.x, hv.y, hv.z, hv.w};
#pragma unroll
                for (int i = 0; i < 4; i++)
#pragma unroll
                    for (int j = 0; j < NT; j++) acc[i][j] += hvv[i] * wv[j];
            }
        }

#pragma unroll
        for (int i = 0; i < 4; i++) {
            int m = my * 4 + i;
#pragma unroll
            for (int j = 0; j < NT; j++) gate_s[m * NS + nx * NT + j] = acc[i][j];
        }
        __syncthreads();

        const float* xgt = xg + (size_t)t * 64 * G;
#pragma unroll
        for (int j = 0; j < U / 2; j++) {
            int p = j * 128 + tid;
            int uu = p % U;
            int m  = p / U;
            int unit = u0 + uu;
            float hval = 0.f;
            if (unit < H) {
                const float* xr = xgt + (size_t)m * G + unit;
                float iraw = gate_s[m * NS + 0 * U + uu] + xr[0];
                float fraw = gate_s[m * NS + 1 * U + uu] + xr[H];
                float graw = gate_s[m * NS + 2 * U + uu] + xr[2 * H];
                float oraw = gate_s[m * NS + 3 * U + uu] + xr[3 * H];
                float cold = cs[m * (U + 1) + uu];
                float cnew = sigmoidf_(fraw) * cold + sigmoidf_(iraw) * tanhf(graw);
                cs[m * (U + 1) + uu] = cnew;
                hval = sigmoidf_(oraw) * tanhf(cnew);
                out[((size_t)t * 64 + m) * H + unit] = hval;
            }
            hw[(u0 + uu) * 64 + m] = hval;
        }
        grid_barrier(nb);
    }
}

// ================= launch =================
extern "C" void kernel_launch(void* const* d_in, const int* in_sizes, int n_in,
                              void* d_out, int out_size)
{
    (void)in_sizes; (void)n_in; (void)out_size;
    const int*   tok = (const int*)d_in[0];
    const float* ew  = (const float*)d_in[1];
    const float* wih[3] = {(const float*)d_in[2], (const float*)d_in[6],  (const float*)d_in[10]};
    const float* whh[3] = {(const float*)d_in[3], (const float*)d_in[7],  (const float*)d_in[11]};
    const float* bih[3] = {(const float*)d_in[4], (const float*)d_in[8],  (const float*)d_in[12]};
    const float* bhh[3] = {(const float*)d_in[5], (const float*)d_in[9],  (const float*)d_in[13]};

    float* out  = (float*)d_out;
    float* out0 = out;
    float* out1 = out0 + (size_t)TB * NHID;
    float* out2 = out1 + (size_t)TB * NHID;

    void* p;
    cudaGetSymbolAddress(&p, g_emb); const float* embf = (const float*)p;
    cudaGetSymbolAddress(&p, g_xg);  float* xgf = (float*)p;
    cudaGetSymbolAddress(&p, g_xh);  __nv_bfloat16* xh = (__nv_bfloat16*)p;
    cudaGetSymbolAddress(&p, g_xl);  __nv_bfloat16* xl = (__nv_bfloat16*)p;
    cudaGetSymbolAddress(&p, g_wh);  __nv_bfloat16* wh = (__nv_bfloat16*)p;
    cudaGetSymbolAddress(&p, g_wl);  __nv_bfloat16* wl = (__nv_bfloat16*)p;

    const int SMEM0 = (1152 * 32 + 64 * 64 + 64 * 33 + 64 * 9) * 4;   // 174,592 B
    const int SMEM2 = (448 * 16 + 64 * 64 + 64 * 17 + 64 * 5) * 4;    //  50,688 B
    cudaFuncSetAttribute(scan_kernel<1150, 1152, 8, 4>,
                         cudaFuncAttributeMaxDynamicSharedMemorySize, SMEM0);
    cudaFuncSetAttribute(scan_kernel<400, 448, 4, 2>,
                         cudaFuncAttributeMaxDynamicSharedMemorySize, SMEM2);

    embed_kernel<<<(TB * 100 + 255) / 256, 256>>>(tok, ew);

    const int ZN = 1152 * 64;
    auto cdiv = [](size_t a, int b) { return (int)((a + b - 1) / b); };

    // ---- layer 0: 400 -> 1150 (KP=448, NP=4608, Nreal=4600) ----
    conv_x_kernel<<<cdiv((size_t)TB * 448, 256), 256>>>(embf, EMB, 448, xh, xl);
    conv_w_kernel<<<cdiv(4608ull * 448, 256), 256>>>(wih[0], 4 * NHID, EMB, 448, 4608, wh, wl);
    proj_hmma_kernel<448><<<dim3(36, 256), 256>>>(xh, xl, wh, wl, bih[0], bhh[0], xgf, 4 * NHID);
    zero_h_kernel<<<(ZN + 255) / 256, 256>>>(ZN);
    scan_kernel<1150, 1152, 8, 4><<<144, 128, SMEM0>>>(xgf, whh[0], out0, 144);

    // ---- layer 1: 1150 -> 1150 (KP=1152, NP=4608, Nreal=4600) ----
    conv_x_kernel<<<cdiv((size_t)TB * 1152, 256), 256>>>(out0, NHID, 1152, xh, xl);
    conv_w_kernel<<<cdiv(4608ull * 1152, 256), 256>>>(wih[1], 4 * NHID, NHID, 1152, 4608, wh, wl);
    proj_hmma_kernel<1152><<<dim3(36, 256), 256>>>(xh, xl, wh, wl, bih[1], bhh[1], xgf, 4 * NHID);
    zero_h_kernel<<<(ZN + 255) / 256, 256>>>(ZN);
    scan_kernel<1150, 1152, 8, 4><<<144, 128, SMEM0>>>(xgf, whh[1], out1, 144);

    // ---- layer 2: 1150 -> 400 (KP=1152, NP=1664, Nreal=1600) ----
    conv_x_kernel<<<cdiv((size_t)TB * 1152, 256), 256>>>(out1, NHID, 1152, xh, xl);
    conv_w_kernel<<<cdiv(1664ull * 1152, 256), 256>>>(wih[2], 4 * 400, NHID, 1152, 1664, wh, wl);
    proj_hmma_kernel<1152><<<dim3(13, 256), 256>>>(xh, xl, wh, wl, bih[2], bhh[2], xgf, 4 * 400);
    zero_h_kernel<<<(ZN + 255) / 256, 256>>>(ZN);
    scan_kernel<400, 448, 4, 2><<<112, 128, SMEM2>>>(xgf, whh[2], out2, 112);
}

// round 6
// speedup vs baseline: 2.0846x; 1.7006x over previous
#include <cuda_runtime.h>
#include <cuda_bf16.h>
#include <math.h>
#include <stdint.h>

#define T_STEPS 512
#define BATCH   64
#define TB      (T_STEPS*BATCH)   // 32768
#define EMB     400
#define NHID    1150

// ================= PTX helpers (sm_80+ only — no 'a' features!) =================
__device__ __forceinline__ uint32_t smem_u32(const void* p) {
    uint32_t a;
    asm("{ .reg .u64 t; cvta.to.shared.u64 t, %1; cvt.u32.u64 %0, t; }" : "=r"(a) : "l"(p));
    return a;
}
__device__ __forceinline__ void ldsm_x4(uint32_t* r, uint32_t addr) {
    asm volatile("ldmatrix.sync.aligned.m8n8.x4.shared.b16 {%0,%1,%2,%3}, [%4];"
        : "=r"(r[0]), "=r"(r[1]), "=r"(r[2]), "=r"(r[3]) : "r"(addr));
}
__device__ __forceinline__ void ldsm_x2(uint32_t* r, uint32_t addr) {
    asm volatile("ldmatrix.sync.aligned.m8n8.x2.shared.b16 {%0,%1}, [%2];"
        : "=r"(r[0]), "=r"(r[1]) : "r"(addr));
}
__device__ __forceinline__ void mma_bf16(float* c, const uint32_t* a, const uint32_t* b) {
    asm volatile("mma.sync.aligned.m16n8k16.row.col.f32.bf16.bf16.f32 "
        "{%0,%1,%2,%3}, {%4,%5,%6,%7}, {%8,%9}, {%0,%1,%2,%3};"
        : "+f"(c[0]), "+f"(c[1]), "+f"(c[2]), "+f"(c[3])
        : "r"(a[0]), "r"(a[1]), "r"(a[2]), "r"(a[3]), "r"(b[0]), "r"(b[1]));
}
__device__ __forceinline__ void cp_async16(uint32_t s, const void* g) {
    asm volatile("cp.async.cg.shared.global [%0], [%1], 16;" :: "r"(s), "l"(g) : "memory");
}
#define CP_COMMIT() asm volatile("cp.async.commit_group;" ::: "memory")
#define CP_WAIT1()  asm volatile("cp.async.wait_group 1;" ::: "memory")
#define CP_WAIT0()  asm volatile("cp.async.wait_group 0;" ::: "memory")

// ================= scratch (device globals) =================
__device__ float g_emb[TB*EMB];                          // 52.4 MB
__device__ float g_xg[(size_t)TB*4*NHID];                // 603 MB
__device__ unsigned g_count;
__device__ unsigned g_gen;
__device__ __align__(16) __nv_bfloat16 g_xh[(size_t)TB*1152];   // 75.5 MB
__device__ __align__(16) __nv_bfloat16 g_xl[(size_t)TB*1152];   // 75.5 MB
__device__ __align__(16) __nv_bfloat16 g_wh[4608ull*1152];      // 10.6 MB
__device__ __align__(16) __nv_bfloat16 g_wl[4608ull*1152];      // 10.6 MB
__device__ __align__(16) __nv_bfloat16 g_hh[2][64*1152];        // h hi, [m][k], double-buffered
__device__ __align__(16) __nv_bfloat16 g_hl[2][64*1152];        // h lo

// ================= embedding gather =================
__global__ void embed_kernel(const int* __restrict__ tok, const float* __restrict__ ew) {
    int i = blockIdx.x * blockDim.x + threadIdx.x;
    if (i < TB * 100) {
        int r = i / 100, c = i - r * 100;
        const float4* src = (const float4*)(ew + (size_t)tok[r] * EMB);
        ((float4*)g_emb)[(size_t)r * 100 + c] = src[c];
    }
}

// ================= bf16 hi/lo split conversions =================
__global__ void conv_x_kernel(const float* __restrict__ X, int K, int KP,
                              __nv_bfloat16* __restrict__ hi, __nv_bfloat16* __restrict__ lo) {
    size_t idx = (size_t)blockIdx.x * blockDim.x + threadIdx.x;
    if (idx >= (size_t)TB * KP) return;
    int k = (int)(idx % KP);
    size_t r = idx / KP;
    float v = (k < K) ? X[r * K + k] : 0.f;
    __nv_bfloat16 h = __float2bfloat16_rn(v);
    hi[idx] = h;
    lo[idx] = __float2bfloat16_rn(v - __bfloat162float(h));
}
__global__ void conv_w_kernel(const float* __restrict__ W, int N, int K, int KP, int NP,
                              __nv_bfloat16* __restrict__ hi, __nv_bfloat16* __restrict__ lo) {
    size_t idx = (size_t)blockIdx.x * blockDim.x + threadIdx.x;
    if (idx >= (size_t)NP * KP) return;
    int k = (int)(idx % KP);
    size_t n = idx / KP;
    float v = (k < K && n < (size_t)N) ? W[n * K + k] : 0.f;
    __nv_bfloat16 h = __float2bfloat16_rn(v);
    hi[idx] = h;
    lo[idx] = __float2bfloat16_rn(v - __bfloat162float(h));
}

// ================= HMMA projection GEMM (unchanged from R5 win) =================
#define PSTR 40

template<int KP>
__global__ void __launch_bounds__(256, 1) proj_hmma_kernel(
    const __nv_bfloat16* __restrict__ Xhi, const __nv_bfloat16* __restrict__ Xlo,
    const __nv_bfloat16* __restrict__ Whi, const __nv_bfloat16* __restrict__ Wlo,
    const float* __restrict__ bi, const float* __restrict__ bh,
    float* __restrict__ Y, int Nreal)
{
    __shared__ __align__(16) __nv_bfloat16 As[2][128 * PSTR];
    __shared__ __align__(16) __nv_bfloat16 Bs[2][128 * PSTR];

    constexpr int KT0 = KP / 32;
    const int KT = 3 * KT0;

    int tid = threadIdx.x;
    int wid = tid >> 5, lane = tid & 31;
    int warp_m = wid & 1, warp_n = wid >> 1;
    size_t mb = (size_t)blockIdx.y * 128;
    size_t nb = (size_t)blockIdx.x * 128;

    const __nv_bfloat16* Asrc[3] = {Xhi, Xlo, Xhi};
    const __nv_bfloat16* Bsrc[3] = {Whi, Whi, Wlo};

    uint32_t as0 = smem_u32(&As[0][0]);
    uint32_t bs0 = smem_u32(&Bs[0][0]);

    int srow = tid >> 2, sseg = tid & 3;
    int srow1 = (tid + 256) >> 2, sseg1 = (tid + 256) & 3;

    float acc[4][4][4];
#pragma unroll
    for (int i = 0; i < 4; i++)
#pragma unroll
        for (int j = 0; j < 4; j++)
#pragma unroll
            for (int q = 0; q < 4; q++) acc[i][j][q] = 0.f;

    {
        const __nv_bfloat16* ax = Asrc[0];
        const __nv_bfloat16* bx = Bsrc[0];
        *(uint4*)&As[0][srow * PSTR + sseg * 8]   = *(const uint4*)(ax + (mb + srow) * KP + sseg * 8);
        *(uint4*)&As[0][srow1 * PSTR + sseg1 * 8] = *(const uint4*)(ax + (mb + srow1) * KP + sseg1 * 8);
        *(uint4*)&Bs[0][srow * PSTR + sseg * 8]   = *(const uint4*)(bx + (nb + srow) * KP + sseg * 8);
        *(uint4*)&Bs[0][srow1 * PSTR + sseg1 * 8] = *(const uint4*)(bx + (nb + srow1) * KP + sseg1 * 8);
    }
    __syncthreads();

    for (int t = 0; t < KT; t++) {
        int cur = t & 1, nxt = cur ^ 1;

        uint4 pa0, pa1, pb0, pb1;
        if (t + 1 < KT) {
            int tp = t + 1;
            int pass = tp / KT0, c = tp - pass * KT0;
            const __nv_bfloat16* ax = Asrc[pass];
            const __nv_bfloat16* bx = Bsrc[pass];
            int col = c * 32;
            pa0 = *(const uint4*)(ax + (mb + srow) * KP + col + sseg * 8);
            pa1 = *(const uint4*)(ax + (mb + srow1) * KP + col + sseg1 * 8);
            pb0 = *(const uint4*)(bx + (nb + srow) * KP + col + sseg * 8);
            pb1 = *(const uint4*)(bx + (nb + srow1) * KP + col + sseg1 * 8);
        }

        uint32_t abase = as0 + cur * (128 * PSTR * 2);
        uint32_t bbase = bs0 + cur * (128 * PSTR * 2);
#pragma unroll
        for (int kf = 0; kf < 2; kf++) {
            uint32_t a[4][4], b[4][2];
#pragma unroll
            for (int fm = 0; fm < 4; fm++) {
                uint32_t addr = abase +
                    ((warp_m * 64 + fm * 16 + (lane & 15)) * PSTR + kf * 16 + (lane >> 4) * 8) * 2;
                ldsm_x4(a[fm], addr);
            }
#pragma unroll
            for (int fn = 0; fn < 4; fn++) {
                uint32_t addr = bbase +
                    ((warp_n * 32 + fn * 8 + (lane & 7)) * PSTR + kf * 16 + ((lane >> 3) & 1) * 8) * 2;
                ldsm_x2(b[fn], addr);
            }
#pragma unroll
            for (int fm = 0; fm < 4; fm++)
#pragma unroll
                for (int fn = 0; fn < 4; fn++)
                    mma_bf16(acc[fm][fn], a[fm], b[fn]);
        }

        if (t + 1 < KT) {
            *(uint4*)&As[nxt][srow * PSTR + sseg * 8]   = pa0;
            *(uint4*)&As[nxt][srow1 * PSTR + sseg1 * 8] = pa1;
            *(uint4*)&Bs[nxt][srow * PSTR + sseg * 8]   = pb0;
            *(uint4*)&Bs[nxt][srow1 * PSTR + sseg1 * 8] = pb1;
        }
        __syncthreads();
    }

    int group = lane >> 2, tig = lane & 3;
#pragma unroll
    for (int fn = 0; fn < 4; fn++) {
        int n = (int)nb + warp_n * 32 + fn * 8 + 2 * tig;
        if (n < Nreal) {
            float bx = bi[n] + bh[n];
            float by = bi[n + 1] + bh[n + 1];
#pragma unroll
            for (int fm = 0; fm < 4; fm++) {
                size_t m = mb + warp_m * 64 + fm * 16 + group;
                float2 v0 = {acc[fm][fn][0] + bx, acc[fm][fn][1] + by};
                *(float2*)&Y[m * (size_t)Nreal + n] = v0;
                float2 v1 = {acc[fm][fn][2] + bx, acc[fm][fn][3] + by};
                *(float2*)&Y[(m + 8) * (size_t)Nreal + n] = v1;
            }
        }
    }
}

// ================= zero bf16 hidden-state buffers (both phases) =================
__global__ void zero_hb_kernel() {
    int i = blockIdx.x * blockDim.x + threadIdx.x;
    if (i < 2 * 64 * 1152 / 2) {
        ((uint32_t*)g_hh)[i] = 0u;
        ((uint32_t*)g_hl)[i] = 0u;
    }
}

// ================= grid barrier =================
__device__ __forceinline__ void grid_barrier(int nb) {
    __threadfence();
    __syncthreads();
    if (threadIdx.x == 0) {
        volatile unsigned* genp = &g_gen;
        unsigned g = *genp;
        unsigned old = atomicAdd(&g_count, 1u);
        if (old == (unsigned)(nb - 1)) {
            g_count = 0;
            __threadfence();
            atomicAdd(&g_gen, 1u);
        } else {
            while (*genp == g) { }
        }
    }
    __syncthreads();
    __threadfence();
}

__device__ __forceinline__ float sigmoidf_(float x) { return 1.f / (1.f + expf(-x)); }

// ================= HMMA persistent LSTM scan =================
// Block owns 8 hidden units (u0..u0+7) x 4 gates = 32 gate rows, ordered n = q*8+ui.
// 4 warps, warp w = m16 rows [w*16, w*16+16) of batch 64. bf16x3 via 3 mma per frag.
// Lane layout (mma C frag): lane = g8*4+tig holds (m = g8, g8+8) x (units 2tig, 2tig+1)
// for ALL 4 gates -> LSTM cell entirely in registers.
__device__ __forceinline__ void stage_chunk(
    uint32_t ah_base, uint32_t al_base,
    const __nv_bfloat16* __restrict__ hh, const __nv_bfloat16* __restrict__ hl,
    int cc, int b, int srow, int sseg)
{
#pragma unroll
    for (int i = 0; i < 8; i++) {
        int row = i * 8 + srow;
        size_t go = (size_t)row * 1152 + cc + sseg * 8;
        uint32_t so = (uint32_t)(((b * 64 + row) * 136 + sseg * 8) * 2);
        cp_async16(ah_base + so, hh + go);
        cp_async16(al_base + so, hl + go);
    }
}

template<int H, int KP>
__global__ void __launch_bounds__(128, 1) scan_hmma_kernel(
    const float* __restrict__ xg,
    const __nv_bfloat16* __restrict__ whh_hi,
    const __nv_bfloat16* __restrict__ whh_lo,
    float* __restrict__ out, int nb)
{
    constexpr int WSTR = KP + 8;     // halves
    constexpr int ASTR = 136;        // halves (128 + 8)
    constexpr int NCH  = KP / 128;
    constexpr int G    = 4 * H;
    constexpr int SEGS = KP / 8;

    extern __shared__ __align__(16) char smx[];
    __nv_bfloat16* Wh = (__nv_bfloat16*)smx;
    __nv_bfloat16* Wl = Wh + 32 * WSTR;
    __nv_bfloat16* Ah = Wl + 32 * WSTR;          // [2][64][ASTR]
    __nv_bfloat16* Al = Ah + 2 * 64 * ASTR;

    int tid = threadIdx.x;
    int w = tid >> 5, lane = tid & 31;
    int g8 = lane >> 2, tig = lane & 3;
    int u0 = blockIdx.x * 8;
    bool uvalid = (u0 + 2 * tig) < H;            // H even: pairs never straddle

    // ---- load W_hh hi/lo into SMEM (resident across all timesteps) ----
    for (int idx = tid; idx < 32 * SEGS; idx += 128) {
        int n = idx / SEGS, seg = idx - n * SEGS;
        int q = n >> 3, ui = n & 7, unit = u0 + ui;
        uint4 vh = {0,0,0,0}, vl = {0,0,0,0};
        if (unit < H) {
            size_t go = (size_t)(q * H + unit) * KP + seg * 8;
            vh = *(const uint4*)(whh_hi + go);
            vl = *(const uint4*)(whh_lo + go);
        }
        *(uint4*)&Wh[n * WSTR + seg * 8] = vh;
        *(uint4*)&Wl[n * WSTR + seg * 8] = vl;
    }
    __syncthreads();

    uint32_t wh_base = smem_u32(Wh), wl_base = smem_u32(Wl);
    uint32_t ah_base = smem_u32(Ah), al_base = smem_u32(Al);

    int srow = tid >> 4, sseg = tid & 15;        // staging decomposition
    float cst[4] = {0.f, 0.f, 0.f, 0.f};         // cell state, register-resident

    for (int t = 0; t < T_STEPS; t++) {
        const __nv_bfloat16* hh = g_hh[t & 1];
        const __nv_bfloat16* hl = g_hl[t & 1];

        float acc[4][4];
#pragma unroll
        for (int q = 0; q < 4; q++)
#pragma unroll
            for (int j = 0; j < 4; j++) acc[q][j] = 0.f;

        // prefetch xg for this step (independent of h)
        float2 xv[8];
#pragma unroll
        for (int mi = 0; mi < 2; mi++)
#pragma unroll
            for (int q = 0; q < 4; q++) {
                xv[mi * 4 + q] = make_float2(0.f, 0.f);
                if (uvalid) {
                    int m = w * 16 + g8 + mi * 8;
                    xv[mi * 4 + q] = *(const float2*)(xg + ((size_t)t * 64 + m) * G
                                                      + q * H + u0 + 2 * tig);
                }
            }

        stage_chunk(ah_base, al_base, hh, hl, 0, 0, srow, sseg);
        CP_COMMIT();

        for (int c = 0; c < NCH; c++) {
            if (c + 1 < NCH) {
                stage_chunk(ah_base, al_base, hh, hl, (c + 1) * 128, (c + 1) & 1, srow, sseg);
                CP_COMMIT();
                CP_WAIT1();
            } else {
                CP_WAIT0();
            }
            __syncthreads();
            int b = c & 1;
#pragma unroll
            for (int j = 0; j < 8; j++) {
                int kc = c * 128 + j * 16;
                uint32_t ah[4], al[4];
                uint32_t a_off = (uint32_t)(((b * 64 + w * 16 + (lane & 15)) * ASTR
                                  + j * 16 + (lane >> 4) * 8) * 2);
                ldsm_x4(ah, ah_base + a_off);
                ldsm_x4(al, al_base + a_off);
#pragma unroll
                for (int nf = 0; nf < 4; nf++) {
                    uint32_t bh[2], bl[2];
                    uint32_t b_off = (uint32_t)(((nf * 8 + (lane & 7)) * WSTR
                                      + kc + ((lane >> 3) & 1) * 8) * 2);
                    ldsm_x2(bh, wh_base + b_off);
                    ldsm_x2(bl, wl_base + b_off);
                    mma_bf16(acc[nf], ah, bh);   // hi*hi
                    mma_bf16(acc[nf], al, bh);   // lo*hi
                    mma_bf16(acc[nf], ah, bl);   // hi*lo
                }
            }
            __syncthreads();
        }

        // ---- epilogue: LSTM cell in registers, write h (fp32 out + bf16 hi/lo) ----
        __nv_bfloat16* hhw = g_hh[(t + 1) & 1];
        __nv_bfloat16* hlw = g_hl[(t + 1) & 1];
#pragma unroll
        for (int mi = 0; mi < 2; mi++) {
            float hv[2];
#pragma unroll
            for (int uu = 0; uu < 2; uu++) {
                float xi = uu ? xv[mi * 4 + 0].y : xv[mi * 4 + 0].x;
                float xf = uu ? xv[mi * 4 + 1].y : xv[mi * 4 + 1].x;
                float xgg = uu ? xv[mi * 4 + 2].y : xv[mi * 4 + 2].x;
                float xo = uu ? xv[mi * 4 + 3].y : xv[mi * 4 + 3].x;
                float iraw = acc[0][mi * 2 + uu] + xi;
                float fraw = acc[1][mi * 2 + uu] + xf;
                float graw = acc[2][mi * 2 + uu] + xgg;
                float oraw = acc[3][mi * 2 + uu] + xo;
                float cn = sigmoidf_(fraw) * cst[mi * 2 + uu]
                         + sigmoidf_(iraw) * tanhf(graw);
                cst[mi * 2 + uu] = cn;
                hv[uu] = sigmoidf_(oraw) * tanhf(cn);
            }
            if (uvalid) {
                int m = w * 16 + g8 + mi * 8;
                *(float2*)&out[((size_t)t * 64 + m) * H + u0 + 2 * tig]
                    = make_float2(hv[0], hv[1]);
                unsigned short h0 = __bfloat16_as_ushort(__float2bfloat16_rn(hv[0]));
                unsigned short h1 = __bfloat16_as_ushort(__float2bfloat16_rn(hv[1]));
                float r0 = hv[0] - __bfloat162float(__ushort_as_bfloat16(h0));
                float r1 = hv[1] - __bfloat162float(__ushort_as_bfloat16(h1));
                unsigned short l0 = __bfloat16_as_ushort(__float2bfloat16_rn(r0));
                unsigned short l1 = __bfloat16_as_ushort(__float2bfloat16_rn(r1));
                *(uint32_t*)&hhw[(size_t)m * 1152 + u0 + 2 * tig]
                    = (uint32_t)h0 | ((uint32_t)h1 << 16);
                *(uint32_t*)&hlw[(size_t)m * 1152 + u0 + 2 * tig]
                    = (uint32_t)l0 | ((uint32_t)l1 << 16);
            }
        }
        grid_barrier(nb);
    }
}

// ================= launch =================
extern "C" void kernel_launch(void* const* d_in, const int* in_sizes, int n_in,
                              void* d_out, int out_size)
{
    (void)in_sizes; (void)n_in; (void)out_size;
    const int*   tok = (const int*)d_in[0];
    const float* ew  = (const float*)d_in[1];
    const float* wih[3] = {(const float*)d_in[2], (const float*)d_in[6],  (const float*)d_in[10]};
    const float* whh[3] = {(const float*)d_in[3], (const float*)d_in[7],  (const float*)d_in[11]};
    const float* bih[3] = {(const float*)d_in[4], (const float*)d_in[8],  (const float*)d_in[12]};
    const float* bhh[3] = {(const float*)d_in[5], (const float*)d_in[9],  (const float*)d_in[13]};

    float* out  = (float*)d_out;
    float* out0 = out;
    float* out1 = out0 + (size_t)TB * NHID;
    float* out2 = out1 + (size_t)TB * NHID;

    void* p;
    cudaGetSymbolAddress(&p, g_emb); const float* embf = (const float*)p;
    cudaGetSymbolAddress(&p, g_xg);  float* xgf = (float*)p;
    cudaGetSymbolAddress(&p, g_xh);  __nv_bfloat16* xh = (__nv_bfloat16*)p;
    cudaGetSymbolAddress(&p, g_xl);  __nv_bfloat16* xl = (__nv_bfloat16*)p;
    cudaGetSymbolAddress(&p, g_wh);  __nv_bfloat16* wh = (__nv_bfloat16*)p;
    cudaGetSymbolAddress(&p, g_wl);  __nv_bfloat16* wl = (__nv_bfloat16*)p;

    // dynamic SMEM for scans: W(2x32x(KP+8)x2B) + A(2bufx2x64x136x2B = 69632)
    const int SSM_BIG = 2 * 32 * (1152 + 8) * 2 + 69632;   // 218,112 B
    const int SSM_SM  = 2 * 32 * (512 + 8) * 2 + 69632;    // 136,192 B
    cudaFuncSetAttribute(scan_hmma_kernel<1150, 1152>,
                         cudaFuncAttributeMaxDynamicSharedMemorySize, SSM_BIG);
    cudaFuncSetAttribute(scan_hmma_kernel<400, 512>,
                         cudaFuncAttributeMaxDynamicSharedMemorySize, SSM_SM);

    embed_kernel<<<(TB * 100 + 255) / 256, 256>>>(tok, ew);

    auto cdiv = [](size_t a, int b) { return (int)((a + b - 1) / b); };
    const int ZHB = (2 * 64 * 1152 / 2 + 255) / 256;

    // ---- layer 0: 400 -> 1150 ----
    conv_x_kernel<<<cdiv((size_t)TB * 448, 256), 256>>>(embf, EMB, 448, xh, xl);
    conv_w_kernel<<<cdiv(4608ull * 448, 256), 256>>>(wih[0], 4 * NHID, EMB, 448, 4608, wh, wl);
    proj_hmma_kernel<448><<<dim3(36, 256), 256>>>(xh, xl, wh, wl, bih[0], bhh[0], xgf, 4 * NHID);
    conv_w_kernel<<<cdiv(4608ull * 1152, 256), 256>>>(whh[0], 4 * NHID, NHID, 1152, 4608, wh, wl);
    zero_hb_kernel<<<ZHB, 256>>>();
    scan_hmma_kernel<1150, 1152><<<144, 128, SSM_BIG>>>(xgf, wh, wl, out0, 144);

    // ---- layer 1: 1150 -> 1150 ----
    conv_x_kernel<<<cdiv((size_t)TB * 1152, 256), 256>>>(out0, NHID, 1152, xh, xl);
    conv_w_kernel<<<cdiv(4608ull * 1152, 256), 256>>>(wih[1], 4 * NHID, NHID, 1152, 4608, wh, wl);
    proj_hmma_kernel<1152><<<dim3(36, 256), 256>>>(xh, xl, wh, wl, bih[1], bhh[1], xgf, 4 * NHID);
    conv_w_kernel<<<cdiv(4608ull * 1152, 256), 256>>>(whh[1], 4 * NHID, NHID, 1152, 4608, wh, wl);
    zero_hb_kernel<<<ZHB, 256>>>();
    scan_hmma_kernel<1150, 1152><<<144, 128, SSM_BIG>>>(xgf, wh, wl, out1, 144);

    // ---- layer 2: 1150 -> 400 ----
    conv_x_kernel<<<cdiv((size_t)TB * 1152, 256), 256>>>(out1, NHID, 1152, xh, xl);
    conv_w_kernel<<<cdiv(1664ull * 1152, 256), 256>>>(wih[2], 4 * 400, NHID, 1152, 1664, wh, wl);
    proj_hmma_kernel<1152><<<dim3(13, 256), 256>>>(xh, xl, wh, wl, bih[2], bhh[2], xgf, 4 * 400);
    conv_w_kernel<<<cdiv(1600ull * 512, 256), 256>>>(whh[2], 4 * 400, 400, 512, 1600, wh, wl);
    zero_hb_kernel<<<ZHB, 256>>>();
    scan_hmma_kernel<400, 512><<<50, 128, SSM_SM>>>(xgf, wh, wl, out2, 50);
}

// round 7
// speedup vs baseline: 2.3359x; 1.1206x over previous
#include <cuda_runtime.h>
#include <cuda_bf16.h>
#include <math.h>
#include <stdint.h>

#define T_STEPS 512
#define BATCH   64
#define TB      (T_STEPS*BATCH)   // 32768
#define EMB     400
#define NHID    1150

// ================= PTX helpers (sm_80+ only — no 'a' features!) =================
__device__ __forceinline__ uint32_t smem_u32(const void* p) {
    uint32_t a;
    asm("{ .reg .u64 t; cvta.to.shared.u64 t, %1; cvt.u32.u64 %0, t; }" : "=r"(a) : "l"(p));
    return a;
}
__device__ __forceinline__ void ldsm_x4(uint32_t* r, uint32_t addr) {
    asm volatile("ldmatrix.sync.aligned.m8n8.x4.shared.b16 {%0,%1,%2,%3}, [%4];"
        : "=r"(r[0]), "=r"(r[1]), "=r"(r[2]), "=r"(r[3]) : "r"(addr));
}
__device__ __forceinline__ void ldsm_x2(uint32_t* r, uint32_t addr) {
    asm volatile("ldmatrix.sync.aligned.m8n8.x2.shared.b16 {%0,%1}, [%2];"
        : "=r"(r[0]), "=r"(r[1]) : "r"(addr));
}
__device__ __forceinline__ void mma_bf16(float* c, const uint32_t* a, const uint32_t* b) {
    asm volatile("mma.sync.aligned.m16n8k16.row.col.f32.bf16.bf16.f32 "
        "{%0,%1,%2,%3}, {%4,%5,%6,%7}, {%8,%9}, {%0,%1,%2,%3};"
        : "+f"(c[0]), "+f"(c[1]), "+f"(c[2]), "+f"(c[3])
        : "r"(a[0]), "r"(a[1]), "r"(a[2]), "r"(a[3]), "r"(b[0]), "r"(b[1]));
}
__device__ __forceinline__ void cp_async16(uint32_t s, const void* g) {
    asm volatile("cp.async.cg.shared.global [%0], [%1], 16;" :: "r"(s), "l"(g) : "memory");
}
#define CP_COMMIT() asm volatile("cp.async.commit_group;" ::: "memory")
#define CP_WAIT1()  asm volatile("cp.async.wait_group 1;" ::: "memory")
#define CP_WAIT0()  asm volatile("cp.async.wait_group 0;" ::: "memory")

// ================= scratch (device globals) =================
__device__ float g_xg[(size_t)TB*4*NHID];                // 603 MB
__device__ unsigned g_count;
__device__ unsigned g_gen;
__device__ __align__(16) __nv_bfloat16 g_xh[(size_t)TB*1152];   // 75.5 MB
__device__ __align__(16) __nv_bfloat16 g_xl[(size_t)TB*1152];   // 75.5 MB
__device__ __align__(16) __nv_bfloat16 g_wh[4608ull*1152];      // 10.6 MB
__device__ __align__(16) __nv_bfloat16 g_wl[4608ull*1152];      // 10.6 MB
__device__ __align__(16) __nv_bfloat16 g_hh[2][64*1152];        // h hi, [m][k]
__device__ __align__(16) __nv_bfloat16 g_hl[2][64*1152];        // h lo

// ================= embedding gather fused with hi/lo split =================
__global__ void embed_split_kernel(const int* __restrict__ tok, const float* __restrict__ ew) {
    int i = blockIdx.x * blockDim.x + threadIdx.x;     // over TB * 112 (448/4 cols)
    if (i >= TB * 112) return;
    int r = i / 112, c4 = i - r * 112;
    float4 v = make_float4(0.f, 0.f, 0.f, 0.f);
    if (c4 < 100) v = *(const float4*)(ew + (size_t)tok[r] * EMB + c4 * 4);
    float vv[4] = {v.x, v.y, v.z, v.w};
    unsigned short h[4], l[4];
#pragma unroll
    for (int j = 0; j < 4; j++) {
        __nv_bfloat16 hb = __float2bfloat16_rn(vv[j]);
        h[j] = __bfloat16_as_ushort(hb);
        l[j] = __bfloat16_as_ushort(__float2bfloat16_rn(vv[j] - __bfloat162float(hb)));
    }
    uint2 uh = make_uint2((uint32_t)h[0] | ((uint32_t)h[1] << 16),
                          (uint32_t)h[2] | ((uint32_t)h[3] << 16));
    uint2 ul = make_uint2((uint32_t)l[0] | ((uint32_t)l[1] << 16),
                          (uint32_t)l[2] | ((uint32_t)l[3] << 16));
    *(uint2*)&g_xh[(size_t)r * 448 + c4 * 4] = uh;
    *(uint2*)&g_xl[(size_t)r * 448 + c4 * 4] = ul;
}

// ================= weight hi/lo split =================
__global__ void conv_w_kernel(const float* __restrict__ W, int N, int K, int KP, int NP,
                              __nv_bfloat16* __restrict__ hi, __nv_bfloat16* __restrict__ lo) {
    size_t idx = (size_t)blockIdx.x * blockDim.x + threadIdx.x;
    if (idx >= (size_t)NP * KP) return;
    int k = (int)(idx % KP);
    size_t n = idx / KP;
    float v = (k < K && n < (size_t)N) ? W[n * K + k] : 0.f;
    __nv_bfloat16 h = __float2bfloat16_rn(v);
    hi[idx] = h;
    lo[idx] = __float2bfloat16_rn(v - __bfloat162float(h));
}

// ================= HMMA projection GEMM v2 =================
// Y[m][n] = sum_k X[m][k]*W[n][k] + bi[n]+bh[n]  via bf16x3.
// 128x128 block tile, 8 warps (2m x 4n). k-chunk 64; each chunk stages
// Ah,Al,Bh,Bl ONCE (cp.async, 2-stage pipeline) and runs all 3 passes on it.
#define TSTR 72                       // smem row stride (halves)
#define PTILE (128*TSTR)              // halves per matrix tile

template<int KP>
__global__ void __launch_bounds__(256, 1) proj_hmma_kernel(
    const __nv_bfloat16* __restrict__ Xhi, const __nv_bfloat16* __restrict__ Xlo,
    const __nv_bfloat16* __restrict__ Whi, const __nv_bfloat16* __restrict__ Wlo,
    const float* __restrict__ bi, const float* __restrict__ bh,
    float* __restrict__ Y, int Nreal)
{
    extern __shared__ __align__(16) __nv_bfloat16 psm[];
    constexpr int KT = KP / 64;

    int tid = threadIdx.x;
    int wid = tid >> 5, lane = tid & 31;
    int warp_m = wid & 1, warp_n = wid >> 1;
    size_t mb = (size_t)blockIdx.y * 128;
    size_t nb = (size_t)blockIdx.x * 128;

    uint32_t sbase = smem_u32(psm);
    int srow = tid >> 3, sseg = tid & 7;

    auto stage = [&](int t) {
        uint32_t b0 = sbase + (uint32_t)(t & 1) * (4 * PTILE * 2);
        int kc = t * 64;
#pragma unroll
        for (int i = 0; i < 4; i++) {
            int row = i * 32 + srow;
            uint32_t so = (uint32_t)((row * TSTR + sseg * 8) * 2);
            size_t ga = (mb + row) * KP + kc + sseg * 8;
            size_t gb = (nb + row) * KP + kc + sseg * 8;
            cp_async16(b0 + so,                 Xhi + ga);
            cp_async16(b0 + PTILE * 2 + so,     Xlo + ga);
            cp_async16(b0 + 2 * PTILE * 2 + so, Whi + gb);
            cp_async16(b0 + 3 * PTILE * 2 + so, Wlo + gb);
        }
    };

    float acc[4][4][4];
#pragma unroll
    for (int i = 0; i < 4; i++)
#pragma unroll
        for (int j = 0; j < 4; j++)
#pragma unroll
            for (int q = 0; q < 4; q++) acc[i][j][q] = 0.f;

    stage(0); CP_COMMIT();

    for (int t = 0; t < KT; t++) {
        if (t + 1 < KT) { stage(t + 1); CP_COMMIT(); CP_WAIT1(); }
        else            { CP_WAIT0(); }
        __syncthreads();

        uint32_t b0 = sbase + (uint32_t)(t & 1) * (4 * PTILE * 2);
#pragma unroll
        for (int kf = 0; kf < 4; kf++) {
            uint32_t ah[4][4], al[4][4], bhf[4][2], blf[4][2];
#pragma unroll
            for (int fm = 0; fm < 4; fm++) {
                uint32_t ao = (uint32_t)(((warp_m * 64 + fm * 16 + (lane & 15)) * TSTR
                               + kf * 16 + (lane >> 4) * 8) * 2);
                ldsm_x4(ah[fm], b0 + ao);
                ldsm_x4(al[fm], b0 + PTILE * 2 + ao);
            }
#pragma unroll
            for (int fn = 0; fn < 4; fn++) {
                uint32_t bo = (uint32_t)(((warp_n * 32 + fn * 8 + (lane & 7)) * TSTR
                               + kf * 16 + ((lane >> 3) & 1) * 8) * 2);
                ldsm_x2(bhf[fn], b0 + 2 * PTILE * 2 + bo);
                ldsm_x2(blf[fn], b0 + 3 * PTILE * 2 + bo);
            }
#pragma unroll
            for (int fm = 0; fm < 4; fm++)
#pragma unroll
                for (int fn = 0; fn < 4; fn++) {
                    mma_bf16(acc[fm][fn], ah[fm], bhf[fn]);   // hi*hi
                    mma_bf16(acc[fm][fn], al[fm], bhf[fn]);   // lo*hi
                    mma_bf16(acc[fm][fn], ah[fm], blf[fn]);   // hi*lo
                }
        }
        __syncthreads();
    }

    // epilogue: fused bias, float2 stores
    int group = lane >> 2, tig = lane & 3;
#pragma unroll
    for (int fn = 0; fn < 4; fn++) {
        int n = (int)nb + warp_n * 32 + fn * 8 + 2 * tig;
        if (n < Nreal) {
            float bx = bi[n] + bh[n];
            float by = bi[n + 1] + bh[n + 1];
#pragma unroll
            for (int fm = 0; fm < 4; fm++) {
                size_t m = mb + warp_m * 64 + fm * 16 + group;
                float2 v0 = {acc[fm][fn][0] + bx, acc[fm][fn][1] + by};
                *(float2*)&Y[m * (size_t)Nreal + n] = v0;
                float2 v1 = {acc[fm][fn][2] + bx, acc[fm][fn][3] + by};
                *(float2*)&Y[(m + 8) * (size_t)Nreal + n] = v1;
            }
        }
    }
}

// ================= zero bf16 hidden-state buffers =================
__global__ void zero_hb_kernel() {
    int i = blockIdx.x * blockDim.x + threadIdx.x;
    if (i < 2 * 64 * 1152 / 2) {
        ((uint32_t*)g_hh)[i] = 0u;
        ((uint32_t*)g_hl)[i] = 0u;
    }
}

// ================= grid barrier =================
__device__ __forceinline__ void grid_barrier(int nb) {
    __threadfence();
    __syncthreads();
    if (threadIdx.x == 0) {
        volatile unsigned* genp = &g_gen;
        unsigned g = *genp;
        unsigned old = atomicAdd(&g_count, 1u);
        if (old == (unsigned)(nb - 1)) {
            g_count = 0;
            __threadfence();
            atomicAdd(&g_gen, 1u);
        } else {
            while (*genp == g) { }
        }
    }
    __syncthreads();
    __threadfence();
}

__device__ __forceinline__ float sigmoidf_(float x) { return 1.f / (1.f + expf(-x)); }

// ================= HMMA persistent LSTM scan =================
// Block owns 8 hidden units x 4 gates = 32 gate rows (n = q*8+ui). 4 warps,
// warp w = batch rows [w*16, w*16+16). bf16x3. LSTM cell fully in registers.
// WX: epilogue also emits next layer's X (bf16 hi/lo, 1152-padded).
__device__ __forceinline__ void stage_chunk(
    uint32_t ah_base, uint32_t al_base,
    const __nv_bfloat16* __restrict__ hh, const __nv_bfloat16* __restrict__ hl,
    int cc, int b, int srow, int sseg)
{
#pragma unroll
    for (int i = 0; i < 8; i++) {
        int row = i * 8 + srow;
        size_t go = (size_t)row * 1152 + cc + sseg * 8;
        uint32_t so = (uint32_t)(((b * 64 + row) * 136 + sseg * 8) * 2);
        cp_async16(ah_base + so, hh + go);
        cp_async16(al_base + so, hl + go);
    }
}

template<int H, int KP, bool WX>
__global__ void __launch_bounds__(128, 1) scan_hmma_kernel(
    const float* __restrict__ xg,
    const __nv_bfloat16* __restrict__ whh_hi,
    const __nv_bfloat16* __restrict__ whh_lo,
    float* __restrict__ out, int nb)
{
    constexpr int WSTR = KP + 8;
    constexpr int ASTR = 136;
    constexpr int NCH  = KP / 128;
    constexpr int G    = 4 * H;
    constexpr int SEGS = KP / 8;

    extern __shared__ __align__(16) char smx[];
    __nv_bfloat16* Wh = (__nv_bfloat16*)smx;
    __nv_bfloat16* Wl = Wh + 32 * WSTR;
    __nv_bfloat16* Ah = Wl + 32 * WSTR;          // [2][64][ASTR]
    __nv_bfloat16* Al = Ah + 2 * 64 * ASTR;

    int tid = threadIdx.x;
    int w = tid >> 5, lane = tid & 31;
    int g8 = lane >> 2, tig = lane & 3;
    int u0 = blockIdx.x * 8;
    bool uvalid = (u0 + 2 * tig) < H;

    for (int idx = tid; idx < 32 * SEGS; idx += 128) {
        int n = idx / SEGS, seg = idx - n * SEGS;
        int q = n >> 3, ui = n & 7, unit = u0 + ui;
        uint4 vh = {0,0,0,0}, vl = {0,0,0,0};
        if (unit < H) {
            size_t go = (size_t)(q * H + unit) * KP + seg * 8;
            vh = *(const uint4*)(whh_hi + go);
            vl = *(const uint4*)(whh_lo + go);
        }
        *(uint4*)&Wh[n * WSTR + seg * 8] = vh;
        *(uint4*)&Wl[n * WSTR + seg * 8] = vl;
    }
    __syncthreads();

    uint32_t wh_base = smem_u32(Wh), wl_base = smem_u32(Wl);
    uint32_t ah_base = smem_u32(Ah), al_base = smem_u32(Al);

    int srow = tid >> 4, sseg = tid & 15;
    float cst[4] = {0.f, 0.f, 0.f, 0.f};

    for (int t = 0; t < T_STEPS; t++) {
        const __nv_bfloat16* hh = g_hh[t & 1];
        const __nv_bfloat16* hl = g_hl[t & 1];

        float acc[4][4];
#pragma unroll
        for (int q = 0; q < 4; q++)
#pragma unroll
            for (int j = 0; j < 4; j++) acc[q][j] = 0.f;

        float2 xv[8];
#pragma unroll
        for (int mi = 0; mi < 2; mi++)
#pragma unroll
            for (int q = 0; q < 4; q++) {
                xv[mi * 4 + q] = make_float2(0.f, 0.f);
                if (uvalid) {
                    int m = w * 16 + g8 + mi * 8;
                    xv[mi * 4 + q] = *(const float2*)(xg + ((size_t)t * 64 + m) * G
                                                      + q * H + u0 + 2 * tig);
                }
            }

        stage_chunk(ah_base, al_base, hh, hl, 0, 0, srow, sseg);
        CP_COMMIT();

        for (int c = 0; c < NCH; c++) {
            if (c + 1 < NCH) {
                stage_chunk(ah_base, al_base, hh, hl, (c + 1) * 128, (c + 1) & 1, srow, sseg);
                CP_COMMIT();
                CP_WAIT1();
            } else {
                CP_WAIT0();
            }
            __syncthreads();
            int b = c & 1;
#pragma unroll
            for (int j = 0; j < 8; j++) {
                int kc = c * 128 + j * 16;
                uint32_t ah[4], al[4];
                uint32_t a_off = (uint32_t)(((b * 64 + w * 16 + (lane & 15)) * ASTR
                                  + j * 16 + (lane >> 4) * 8) * 2);
                ldsm_x4(ah, ah_base + a_off);
                ldsm_x4(al, al_base + a_off);
#pragma unroll
                for (int nf = 0; nf < 4; nf++) {
                    uint32_t bh[2], bl[2];
                    uint32_t b_off = (uint32_t)(((nf * 8 + (lane & 7)) * WSTR
                                      + kc + ((lane >> 3) & 1) * 8) * 2);
                    ldsm_x2(bh, wh_base + b_off);
                    ldsm_x2(bl, wl_base + b_off);
                    mma_bf16(acc[nf], ah, bh);
                    mma_bf16(acc[nf], al, bh);
                    mma_bf16(acc[nf], ah, bl);
                }
            }
            __syncthreads();
        }

        __nv_bfloat16* hhw = g_hh[(t + 1) & 1];
        __nv_bfloat16* hlw = g_hl[(t + 1) & 1];
#pragma unroll
        for (int mi = 0; mi < 2; mi++) {
            float hv[2];
#pragma unroll
            for (int uu = 0; uu < 2; uu++) {
                float xi = uu ? xv[mi * 4 + 0].y : xv[mi * 4 + 0].x;
                float xf = uu ? xv[mi * 4 + 1].y : xv[mi * 4 + 1].x;
                float xgg = uu ? xv[mi * 4 + 2].y : xv[mi * 4 + 2].x;
                float xo = uu ? xv[mi * 4 + 3].y : xv[mi * 4 + 3].x;
                float iraw = acc[0][mi * 2 + uu] + xi;
                float fraw = acc[1][mi * 2 + uu] + xf;
                float graw = acc[2][mi * 2 + uu] + xgg;
                float oraw = acc[3][mi * 2 + uu] + xo;
                float cn = sigmoidf_(fraw) * cst[mi * 2 + uu]
                         + sigmoidf_(iraw) * tanhf(graw);
                cst[mi * 2 + uu] = cn;
                hv[uu] = sigmoidf_(oraw) * tanhf(cn);
            }
            int m = w * 16 + g8 + mi * 8;
            uint32_t packed_h = 0u, packed_l = 0u;
            if (uvalid) {
                *(float2*)&out[((size_t)t * 64 + m) * H + u0 + 2 * tig]
                    = make_float2(hv[0], hv[1]);
                unsigned short h0 = __bfloat16_as_ushort(__float2bfloat16_rn(hv[0]));
                unsigned short h1 = __bfloat16_as_ushort(__float2bfloat16_rn(hv[1]));
                float r0 = hv[0] - __bfloat162float(__ushort_as_bfloat16(h0));
                float r1 = hv[1] - __bfloat162float(__ushort_as_bfloat16(h1));
                unsigned short l0 = __bfloat16_as_ushort(__float2bfloat16_rn(r0));
                unsigned short l1 = __bfloat16_as_ushort(__float2bfloat16_rn(r1));
                packed_h = (uint32_t)h0 | ((uint32_t)h1 << 16);
                packed_l = (uint32_t)l0 | ((uint32_t)l1 << 16);
                *(uint32_t*)&hhw[(size_t)m * 1152 + u0 + 2 * tig] = packed_h;
                *(uint32_t*)&hlw[(size_t)m * 1152 + u0 + 2 * tig] = packed_l;
            }
            if (WX) {   // next layer's X, 1152-padded (zeros where invalid)
                size_t xrow = ((size_t)t * 64 + m) * 1152 + u0 + 2 * tig;
                *(uint32_t*)&g_xh[xrow] = packed_h;
                *(uint32_t*)&g_xl[xrow] = packed_l;
            }
        }
        grid_barrier(nb);
    }
}

// ================= launch =================
extern "C" void kernel_launch(void* const* d_in, const int* in_sizes, int n_in,
                              void* d_out, int out_size)
{
    (void)in_sizes; (void)n_in; (void)out_size;
    const int*   tok = (const int*)d_in[0];
    const float* ew  = (const float*)d_in[1];
    const float* wih[3] = {(const float*)d_in[2], (const float*)d_in[6],  (const float*)d_in[10]};
    const float* whh[3] = {(const float*)d_in[3], (const float*)d_in[7],  (const float*)d_in[11]};
    const float* bih[3] = {(const float*)d_in[4], (const float*)d_in[8],  (const float*)d_in[12]};
    const float* bhh[3] = {(const float*)d_in[5], (const float*)d_in[9],  (const float*)d_in[13]};

    float* out  = (float*)d_out;
    float* out0 = out;
    float* out1 = out0 + (size_t)TB * NHID;
    float* out2 = out1 + (size_t)TB * NHID;

    void* p;
    cudaGetSymbolAddress(&p, g_xg);  float* xgf = (float*)p;
    cudaGetSymbolAddress(&p, g_xh);  __nv_bfloat16* xh = (__nv_bfloat16*)p;
    cudaGetSymbolAddress(&p, g_xl);  __nv_bfloat16* xl = (__nv_bfloat16*)p;
    cudaGetSymbolAddress(&p, g_wh);  __nv_bfloat16* wh = (__nv_bfloat16*)p;
    cudaGetSymbolAddress(&p, g_wl);  __nv_bfloat16* wl = (__nv_bfloat16*)p;

    const int PSM     = 2 * 4 * PTILE * 2;                 // 147,456 B
    const int SSM_BIG = 2 * 32 * (1152 + 8) * 2 + 69632;   // 218,112 B
    const int SSM_SM  = 2 * 32 * (512 + 8) * 2 + 69632;    // 136,192 B
    cudaFuncSetAttribute(proj_hmma_kernel<448>,
                         cudaFuncAttributeMaxDynamicSharedMemorySize, PSM);
    cudaFuncSetAttribute(proj_hmma_kernel<1152>,
                         cudaFuncAttributeMaxDynamicSharedMemorySize, PSM);
    cudaFuncSetAttribute(scan_hmma_kernel<1150, 1152, true>,
                         cudaFuncAttributeMaxDynamicSharedMemorySize, SSM_BIG);
    cudaFuncSetAttribute(scan_hmma_kernel<400, 512, false>,
                         cudaFuncAttributeMaxDynamicSharedMemorySize, SSM_SM);

    auto cdiv = [](size_t a, int b) { return (int)((a + b - 1) / b); };
    const int ZHB = (2 * 64 * 1152 / 2 + 255) / 256;

    // embedding -> xh/xl (KP=448), fused split
    embed_split_kernel<<<cdiv((size_t)TB * 112, 256), 256>>>(tok, ew);

    // ---- layer 0: 400 -> 1150 ----
    conv_w_kernel<<<cdiv(4608ull * 448, 256), 256>>>(wih[0], 4 * NHID, EMB, 448, 4608, wh, wl);
    proj_hmma_kernel<448><<<dim3(36, 256), 256, PSM>>>(xh, xl, wh, wl, bih[0], bhh[0], xgf, 4 * NHID);
    conv_w_kernel<<<cdiv(4608ull * 1152, 256), 256>>>(whh[0], 4 * NHID, NHID, 1152, 4608, wh, wl);
    zero_hb_kernel<<<ZHB, 256>>>();
    scan_hmma_kernel<1150, 1152, true><<<144, 128, SSM_BIG>>>(xgf, wh, wl, out0, 144);

    // ---- layer 1: 1150 -> 1150 ----  (X written by scan0)
    conv_w_kernel<<<cdiv(4608ull * 1152, 256), 256>>>(wih[1], 4 * NHID, NHID, 1152, 4608, wh, wl);
    proj_hmma_kernel<1152><<<dim3(36, 256), 256, PSM>>>(xh, xl, wh, wl, bih[1], bhh[1], xgf, 4 * NHID);
    conv_w_kernel<<<cdiv(4608ull * 1152, 256), 256>>>(whh[1], 4 * NHID, NHID, 1152, 4608, wh, wl);
    zero_hb_kernel<<<ZHB, 256>>>();
    scan_hmma_kernel<1150, 1152, true><<<144, 128, SSM_BIG>>>(xgf, wh, wl, out1, 144);

    // ---- layer 2: 1150 -> 400 ----  (X written by scan1)
    conv_w_kernel<<<cdiv(1664ull * 1152, 256), 256>>>(wih[2], 4 * 400, NHID, 1152, 1664, wh, wl);
    proj_hmma_kernel<1152><<<dim3(13, 256), 256, PSM>>>(xh, xl, wh, wl, bih[2], bhh[2], xgf, 4 * 400);
    conv_w_kernel<<<cdiv(1600ull * 512, 256), 256>>>(whh[2], 4 * 400, 400, 512, 1600, wh, wl);
    zero_hb_kernel<<<ZHB, 256>>>();
    scan_hmma_kernel<400, 512, false><<<50, 128, SSM_SM>>>(xgf, wh, wl, out2, 50);
}